// round 3
// baseline (speedup 1.0000x reference)
#include <cuda_runtime.h>
#include <cstdint>

#define BATCH   4
#define NHEAD   12
#define HDIM    64
#define DMODEL  768
#define SEQ     2048

// ---------------- static device scratch (no cudaMalloc allowed) ----------------
__device__ float g_Qp[(size_t)BATCH * SEQ * DMODEL];
__device__ float g_Kp[(size_t)BATCH * SEQ * DMODEL];
__device__ float g_Vp[(size_t)BATCH * SEQ * DMODEL];

// ---------------- helpers ----------------
__device__ __forceinline__ float to_tf32(float x) {
    unsigned u;
    asm("cvt.rna.tf32.f32 %0, %1;" : "=r"(u) : "f"(x));
    return __uint_as_float(u);
}

__device__ __forceinline__ float4 to_tf32_4(float4 v) {
    v.x = to_tf32(v.x); v.y = to_tf32(v.y);
    v.z = to_tf32(v.z); v.w = to_tf32(v.w);
    return v;
}

// D = A(16x8,row) * B(8x8,col) + C, tf32 inputs, f32 accum
__device__ __forceinline__ void mma_tf32(float c[4],
                                         float a0, float a1, float a2, float a3,
                                         float b0, float b1) {
    asm volatile(
        "mma.sync.aligned.m16n8k8.row.col.f32.tf32.tf32.f32 "
        "{%0,%1,%2,%3}, {%4,%5,%6,%7}, {%8,%9}, {%0,%1,%2,%3};\n"
        : "+f"(c[0]), "+f"(c[1]), "+f"(c[2]), "+f"(c[3])
        : "r"(__float_as_uint(a0)), "r"(__float_as_uint(a1)),
          "r"(__float_as_uint(a2)), "r"(__float_as_uint(a3)),
          "r"(__float_as_uint(b0)), "r"(__float_as_uint(b1)));
}

// ================= projection GEMM: C[8192,768] = X[8192,768] @ W[768,768] + bias =================
// BM=128 BN=64 BK=32, 256 threads = 8 warps (4 m x 2 n), warp tile 32x32.
__global__ void __launch_bounds__(256, 2)
proj_kernel(const float* __restrict__ X, const float* __restrict__ W,
            const float* __restrict__ bias, int sel)
{
    float* C = (sel == 0) ? g_Qp : ((sel == 1) ? g_Kp : g_Vp);

    __shared__ float Xs[128 * 36];   // [m][k], stride 36: conflict-free A-frag loads, f4-alignable
    __shared__ float Ws[32 * 72];    // [k][n], stride 72: conflict-free B-frag loads

    const int tid  = threadIdx.x;
    const int warp = tid >> 5, lane = tid & 31;
    const int g = lane >> 2, t = lane & 3;
    const int m0 = blockIdx.x * 128;
    const int n0 = blockIdx.y * 64;
    const int wm = (warp & 3) * 32;
    const int wn = (warp >> 2) * 32;

    float acc[2][4][4];
#pragma unroll
    for (int mi = 0; mi < 2; mi++)
#pragma unroll
        for (int ni = 0; ni < 4; ni++)
#pragma unroll
            for (int c = 0; c < 4; c++) acc[mi][ni][c] = 0.f;

    for (int k0 = 0; k0 < DMODEL; k0 += 32) {
        // X tile: 128x32 floats = 1024 float4, 4 per thread
#pragma unroll
        for (int i = 0; i < 4; i++) {
            int linear = i * 256 + tid;
            int r = linear >> 3;
            int c = (linear & 7) << 2;
            float4 v = *(const float4*)(X + (size_t)(m0 + r) * DMODEL + k0 + c);
            *(float4*)(Xs + r * 36 + c) = to_tf32_4(v);
        }
        // W tile: 32x64 floats = 512 float4, 2 per thread
#pragma unroll
        for (int i = 0; i < 2; i++) {
            int linear = i * 256 + tid;
            int r = linear >> 4;
            int c = (linear & 15) << 2;
            float4 v = *(const float4*)(W + (size_t)(k0 + r) * DMODEL + n0 + c);
            *(float4*)(Ws + r * 72 + c) = to_tf32_4(v);
        }
        __syncthreads();

#pragma unroll
        for (int kk = 0; kk < 4; kk++) {
            int kb = kk * 8;
            float a[2][4];
#pragma unroll
            for (int mi = 0; mi < 2; mi++) {
                int rb = wm + mi * 16;
                a[mi][0] = Xs[(rb + g) * 36 + kb + t];
                a[mi][1] = Xs[(rb + g + 8) * 36 + kb + t];
                a[mi][2] = Xs[(rb + g) * 36 + kb + t + 4];
                a[mi][3] = Xs[(rb + g + 8) * 36 + kb + t + 4];
            }
#pragma unroll
            for (int ni = 0; ni < 4; ni++) {
                float b0 = Ws[(kb + t) * 72 + wn + ni * 8 + g];
                float b1 = Ws[(kb + t + 4) * 72 + wn + ni * 8 + g];
                mma_tf32(acc[0][ni], a[0][0], a[0][1], a[0][2], a[0][3], b0, b1);
                mma_tf32(acc[1][ni], a[1][0], a[1][1], a[1][2], a[1][3], b0, b1);
            }
        }
        __syncthreads();
    }

    // epilogue: + bias, fp32 out
#pragma unroll
    for (int mi = 0; mi < 2; mi++) {
#pragma unroll
        for (int ni = 0; ni < 4; ni++) {
            int row = m0 + wm + mi * 16 + g;
            int col = n0 + wn + ni * 8 + 2 * t;
            float b0v = bias[col], b1v = bias[col + 1];
            float2 v0 = make_float2(acc[mi][ni][0] + b0v, acc[mi][ni][1] + b1v);
            float2 v1 = make_float2(acc[mi][ni][2] + b0v, acc[mi][ni][3] + b1v);
            *(float2*)(C + (size_t)row * DMODEL + col)       = v0;
            *(float2*)(C + (size_t)(row + 8) * DMODEL + col) = v1;
        }
    }
}

// ================= flash attention: one CTA per (head, q-tile=128, batch) =================
#define QTILE     128
#define KTILE     64
#define QS_STRIDE 68
#define KS_STRIDE 68
#define VS_STRIDE 72
#define PS_STRIDE 68
#define ATTN_SMEM ((QTILE*QS_STRIDE + KTILE*KS_STRIDE + KTILE*VS_STRIDE + QTILE*PS_STRIDE) * 4)

__global__ void __launch_bounds__(256, 2)
attn_kernel(const float* __restrict__ mask, float* __restrict__ out)
{
    extern __shared__ float sm[];
    float* Qs = sm;                            // [128][68]  A for S
    float* Ks = Qs + QTILE * QS_STRIDE;        // [64][68]   B for S (K rows, h cols)
    float* Vs = Ks + KTILE * KS_STRIDE;        // [64][72]   B for PV (k rows, h cols)
    float* Ps = Vs + KTILE * VS_STRIDE;        // [128][68]  A for PV

    const int head = blockIdx.x;
    const int q0   = blockIdx.y * QTILE;
    const int b    = blockIdx.z;
    const int tid  = threadIdx.x;
    const int warp = tid >> 5, lane = tid & 31;
    const int g = lane >> 2, t = lane & 3;
    const int wq = warp * 16;                  // this warp owns q rows [wq, wq+16)

    // ---- load Q tile (tf32-rounded): 128x64 = 2048 float4, 8 per thread ----
#pragma unroll
    for (int i = 0; i < 8; i++) {
        int linear = i * 256 + tid;
        int r = linear >> 4;
        int c = (linear & 15) << 2;
        float4 v = *(const float4*)(g_Qp + (size_t)(b * SEQ + q0 + r) * DMODEL + head * HDIM + c);
        *(float4*)(Qs + r * QS_STRIDE + c) = to_tf32_4(v);
    }

    float o[8][4];
#pragma unroll
    for (int j = 0; j < 8; j++)
#pragma unroll
        for (int c = 0; c < 4; c++) o[j][c] = 0.f;

    float m0r = -1e30f, m1r = -1e30f;   // running row max (rows g, g+8)
    float l0r = 0.f,    l1r = 0.f;      // running row sum

    for (int kt = 0; kt < SEQ / KTILE; kt++) {
        const int k0 = kt * KTILE;
        __syncthreads();  // protect Ks/Vs readers from previous iter (and Qs on iter 0)

        // ---- load K,V tiles: 64x64 each = 1024 float4, 4 per thread ----
#pragma unroll
        for (int i = 0; i < 4; i++) {
            int linear = i * 256 + tid;
            int r = linear >> 4;
            int c = (linear & 15) << 2;
            size_t goff = (size_t)(b * SEQ + k0 + r) * DMODEL + head * HDIM + c;
            float4 kv = *(const float4*)(g_Kp + goff);
            *(float4*)(Ks + r * KS_STRIDE + c) = to_tf32_4(kv);
            float4 vv = *(const float4*)(g_Vp + goff);
            *(float4*)(Vs + r * VS_STRIDE + c) = to_tf32_4(vv);
        }
        __syncthreads();

        // ---- S = Q @ K^T : per warp 16x64, 8 n-frags ----
        float s[8][4];
#pragma unroll
        for (int j = 0; j < 8; j++)
#pragma unroll
            for (int c = 0; c < 4; c++) s[j][c] = 0.f;

#pragma unroll
        for (int kk = 0; kk < 8; kk++) {
            int kb = kk * 8;
            float a0 = Qs[(wq + g) * QS_STRIDE + kb + t];
            float a1 = Qs[(wq + g + 8) * QS_STRIDE + kb + t];
            float a2 = Qs[(wq + g) * QS_STRIDE + kb + t + 4];
            float a3 = Qs[(wq + g + 8) * QS_STRIDE + kb + t + 4];
#pragma unroll
            for (int j = 0; j < 8; j++) {
                float b0 = Ks[(j * 8 + g) * KS_STRIDE + kb + t];
                float b1 = Ks[(j * 8 + g) * KS_STRIDE + kb + t + 4];
                mma_tf32(s[j], a0, a1, a2, a3, b0, b1);
            }
        }

        // ---- scale + mask + online softmax ----
        const float* mrow0 = mask + ((size_t)b * SEQ + q0 + wq + g) * SEQ + k0;
        const float* mrow1 = mrow0 + (size_t)8 * SEQ;
        float rmax0 = -1e30f, rmax1 = -1e30f;
#pragma unroll
        for (int j = 0; j < 8; j++) {
            int col = j * 8 + 2 * t;
            s[j][0] = s[j][0] * 0.125f + mrow0[col];
            s[j][1] = s[j][1] * 0.125f + mrow0[col + 1];
            s[j][2] = s[j][2] * 0.125f + mrow1[col];
            s[j][3] = s[j][3] * 0.125f + mrow1[col + 1];
            rmax0 = fmaxf(rmax0, fmaxf(s[j][0], s[j][1]));
            rmax1 = fmaxf(rmax1, fmaxf(s[j][2], s[j][3]));
        }
        rmax0 = fmaxf(rmax0, __shfl_xor_sync(0xffffffffu, rmax0, 1));
        rmax0 = fmaxf(rmax0, __shfl_xor_sync(0xffffffffu, rmax0, 2));
        rmax1 = fmaxf(rmax1, __shfl_xor_sync(0xffffffffu, rmax1, 1));
        rmax1 = fmaxf(rmax1, __shfl_xor_sync(0xffffffffu, rmax1, 2));

        float nm0 = fmaxf(m0r, rmax0), nm1 = fmaxf(m1r, rmax1);
        float alpha0 = __expf(m0r - nm0), alpha1 = __expf(m1r - nm1);
        m0r = nm0; m1r = nm1;

        float sum0 = 0.f, sum1 = 0.f;
#pragma unroll
        for (int j = 0; j < 8; j++) {
            s[j][0] = __expf(s[j][0] - nm0);
            s[j][1] = __expf(s[j][1] - nm0);
            s[j][2] = __expf(s[j][2] - nm1);
            s[j][3] = __expf(s[j][3] - nm1);
            sum0 += s[j][0] + s[j][1];
            sum1 += s[j][2] + s[j][3];
            int col = j * 8 + 2 * t;
            Ps[(wq + g) * PS_STRIDE + col]         = to_tf32(s[j][0]);
            Ps[(wq + g) * PS_STRIDE + col + 1]     = to_tf32(s[j][1]);
            Ps[(wq + g + 8) * PS_STRIDE + col]     = to_tf32(s[j][2]);
            Ps[(wq + g + 8) * PS_STRIDE + col + 1] = to_tf32(s[j][3]);
        }
        sum0 += __shfl_xor_sync(0xffffffffu, sum0, 1);
        sum0 += __shfl_xor_sync(0xffffffffu, sum0, 2);
        sum1 += __shfl_xor_sync(0xffffffffu, sum1, 1);
        sum1 += __shfl_xor_sync(0xffffffffu, sum1, 2);
        l0r = l0r * alpha0 + sum0;
        l1r = l1r * alpha1 + sum1;

#pragma unroll
        for (int j = 0; j < 8; j++) {
            o[j][0] *= alpha0; o[j][1] *= alpha0;
            o[j][2] *= alpha1; o[j][3] *= alpha1;
        }
        __syncwarp();  // each warp reads only its own 16 Ps rows; Vs already synced

        // ---- O += P @ V : k-dim = KTILE, 8 h-frags ----
#pragma unroll
        for (int kk = 0; kk < 8; kk++) {
            int kb = kk * 8;
            float a0 = Ps[(wq + g) * PS_STRIDE + kb + t];
            float a1 = Ps[(wq + g + 8) * PS_STRIDE + kb + t];
            float a2 = Ps[(wq + g) * PS_STRIDE + kb + t + 4];
            float a3 = Ps[(wq + g + 8) * PS_STRIDE + kb + t + 4];
#pragma unroll
            for (int j = 0; j < 8; j++) {
                float b0 = Vs[(kb + t) * VS_STRIDE + j * 8 + g];
                float b1 = Vs[(kb + t + 4) * VS_STRIDE + j * 8 + g];
                mma_tf32(o[j], a0, a1, a2, a3, b0, b1);
            }
        }
    }

    // ---- epilogue: O / l, write [B*Q, N*H] ----
    float inv0 = 1.f / l0r, inv1 = 1.f / l1r;
#pragma unroll
    for (int j = 0; j < 8; j++) {
        int col = head * HDIM + j * 8 + 2 * t;
        size_t row0 = (size_t)(b * SEQ + q0 + wq + g);
        float2 v0 = make_float2(o[j][0] * inv0, o[j][1] * inv0);
        float2 v1 = make_float2(o[j][2] * inv1, o[j][3] * inv1);
        *(float2*)(out + row0 * DMODEL + col)        = v0;
        *(float2*)(out + (row0 + 8) * DMODEL + col)  = v1;
    }
}

// ================= launch =================
extern "C" void kernel_launch(void* const* d_in, const int* in_sizes, int n_in,
                              void* d_out, int out_size) {
    (void)in_sizes; (void)n_in; (void)out_size;
    const float* query = (const float*)d_in[0];
    const float* key   = (const float*)d_in[1];
    const float* value = (const float*)d_in[2];
    const float* mask  = (const float*)d_in[3];
    const float* Wq    = (const float*)d_in[4];
    const float* bq    = (const float*)d_in[5];
    const float* Wk    = (const float*)d_in[6];
    const float* bk    = (const float*)d_in[7];
    const float* Wv    = (const float*)d_in[8];
    const float* bv    = (const float*)d_in[9];
    float* out = (float*)d_out;

    cudaFuncSetAttribute(attn_kernel, cudaFuncAttributeMaxDynamicSharedMemorySize, ATTN_SMEM);

    dim3 pgrid(DMODEL * BATCH * SEQ / (128 * DMODEL), DMODEL / 64);  // (64, 12)
    proj_kernel<<<pgrid, 256>>>(query, Wq, bq, 0);
    proj_kernel<<<pgrid, 256>>>(key,   Wk, bk, 1);
    proj_kernel<<<pgrid, 256>>>(value, Wv, bv, 2);

    dim3 agrid(NHEAD, SEQ / QTILE, BATCH);   // head fastest -> mask L2 reuse across heads
    attn_kernel<<<agrid, 256, ATTN_SMEM>>>(mask, out);
}

// round 4
// speedup vs baseline: 1.2122x; 1.2122x over previous
#include <cuda_runtime.h>
#include <cstdint>

#define BATCH   4
#define NHEAD   12
#define HDIM    64
#define DMODEL  768
#define SEQ     2048

// ---------------- static device scratch (no cudaMalloc allowed) ----------------
__device__ float g_Qp[(size_t)BATCH * SEQ * DMODEL];
__device__ float g_Kp[(size_t)BATCH * SEQ * DMODEL];
__device__ float g_Vp[(size_t)BATCH * SEQ * DMODEL];

// ---------------- helpers ----------------
__device__ __forceinline__ float to_tf32(float x) {
    unsigned u;
    asm("cvt.rna.tf32.f32 %0, %1;" : "=r"(u) : "f"(x));
    return __uint_as_float(u);
}

__device__ __forceinline__ float4 to_tf32_4(float4 v) {
    v.x = to_tf32(v.x); v.y = to_tf32(v.y);
    v.z = to_tf32(v.z); v.w = to_tf32(v.w);
    return v;
}

// D = A(16x8,row) * B(8x8,col) + C, tf32 inputs, f32 accum
// a0=(g,k=t) a1=(g+8,t) a2=(g,t+4) a3=(g+8,t+4); b0=(k=t,n=g) b1=(t+4,g)
__device__ __forceinline__ void mma_tf32(float c[4],
                                         float a0, float a1, float a2, float a3,
                                         float b0, float b1) {
    asm volatile(
        "mma.sync.aligned.m16n8k8.row.col.f32.tf32.tf32.f32 "
        "{%0,%1,%2,%3}, {%4,%5,%6,%7}, {%8,%9}, {%0,%1,%2,%3};\n"
        : "+f"(c[0]), "+f"(c[1]), "+f"(c[2]), "+f"(c[3])
        : "r"(__float_as_uint(a0)), "r"(__float_as_uint(a1)),
          "r"(__float_as_uint(a2)), "r"(__float_as_uint(a3)),
          "r"(__float_as_uint(b0)), "r"(__float_as_uint(b1)));
}

// ================= projection GEMM (merged QKV): grid.z selects proj =================
__global__ void __launch_bounds__(256, 2)
proj_kernel(const float* __restrict__ Xq, const float* __restrict__ Xk, const float* __restrict__ Xv,
            const float* __restrict__ Wqp, const float* __restrict__ Wkp, const float* __restrict__ Wvp,
            const float* __restrict__ bqp, const float* __restrict__ bkp, const float* __restrict__ bvp)
{
    const int sel = blockIdx.z;
    const float* X    = (sel == 0) ? Xq  : (sel == 1) ? Xk  : Xv;
    const float* W    = (sel == 0) ? Wqp : (sel == 1) ? Wkp : Wvp;
    const float* bias = (sel == 0) ? bqp : (sel == 1) ? bkp : bvp;
    float* C          = (sel == 0) ? g_Qp : (sel == 1) ? g_Kp : g_Vp;

    __shared__ float Xs[128 * 36];   // [m][k]
    __shared__ float Ws[32 * 72];    // [k][n]

    const int tid  = threadIdx.x;
    const int warp = tid >> 5, lane = tid & 31;
    const int g = lane >> 2, t = lane & 3;
    const int m0 = blockIdx.x * 128;
    const int n0 = blockIdx.y * 64;
    const int wm = (warp & 3) * 32;
    const int wn = (warp >> 2) * 32;

    float acc[2][4][4];
#pragma unroll
    for (int mi = 0; mi < 2; mi++)
#pragma unroll
        for (int ni = 0; ni < 4; ni++)
#pragma unroll
            for (int c = 0; c < 4; c++) acc[mi][ni][c] = 0.f;

    for (int k0 = 0; k0 < DMODEL; k0 += 32) {
#pragma unroll
        for (int i = 0; i < 4; i++) {
            int linear = i * 256 + tid;
            int r = linear >> 3;
            int c = (linear & 7) << 2;
            float4 v = *(const float4*)(X + (size_t)(m0 + r) * DMODEL + k0 + c);
            *(float4*)(Xs + r * 36 + c) = to_tf32_4(v);
        }
#pragma unroll
        for (int i = 0; i < 2; i++) {
            int linear = i * 256 + tid;
            int r = linear >> 4;
            int c = (linear & 15) << 2;
            float4 v = *(const float4*)(W + (size_t)(k0 + r) * DMODEL + n0 + c);
            *(float4*)(Ws + r * 72 + c) = to_tf32_4(v);
        }
        __syncthreads();

#pragma unroll
        for (int kk = 0; kk < 4; kk++) {
            int kb = kk * 8;
            float a[2][4];
#pragma unroll
            for (int mi = 0; mi < 2; mi++) {
                int rb = wm + mi * 16;
                a[mi][0] = Xs[(rb + g) * 36 + kb + t];
                a[mi][1] = Xs[(rb + g + 8) * 36 + kb + t];
                a[mi][2] = Xs[(rb + g) * 36 + kb + t + 4];
                a[mi][3] = Xs[(rb + g + 8) * 36 + kb + t + 4];
            }
#pragma unroll
            for (int ni = 0; ni < 4; ni++) {
                float b0 = Ws[(kb + t) * 72 + wn + ni * 8 + g];
                float b1 = Ws[(kb + t + 4) * 72 + wn + ni * 8 + g];
                mma_tf32(acc[0][ni], a[0][0], a[0][1], a[0][2], a[0][3], b0, b1);
                mma_tf32(acc[1][ni], a[1][0], a[1][1], a[1][2], a[1][3], b0, b1);
            }
        }
        __syncthreads();
    }

#pragma unroll
    for (int mi = 0; mi < 2; mi++) {
#pragma unroll
        for (int ni = 0; ni < 4; ni++) {
            int row = m0 + wm + mi * 16 + g;
            int col = n0 + wn + ni * 8 + 2 * t;
            float b0v = bias[col], b1v = bias[col + 1];
            float2 v0 = make_float2(acc[mi][ni][0] + b0v, acc[mi][ni][1] + b1v);
            float2 v1 = make_float2(acc[mi][ni][2] + b0v, acc[mi][ni][3] + b1v);
            *(float2*)(C + (size_t)row * DMODEL + col)       = v0;
            *(float2*)(C + (size_t)(row + 8) * DMODEL + col) = v1;
        }
    }
}

// ================= flash attention =================
// Layouts (all strides 72 floats):
//   Qs/Ks "mod-4-major": word(r,c) = r*72 + 18*(c&3) + (c>>2)
//     -> frag pair (c=kb+t, kb+t+4) is one conflict-free LDS.64
//   Vs: rows permuted kappa(r) = (r&~7)|((r&7)>>1)|((r&1)<<2)  [P-as-A-frag trick]
//       cols sigma8: p = 8*(c&7) + (c>>3); 16B block XOR-swizzled by (kappa&3)
//     -> per kk, 4 conflict-free LDS.128 feed all 8 PV mmas
#define QTILE  128
#define KTILE  64
#define ST     72
#define QW     (QTILE * ST)              // 9216 floats
#define TB     (KTILE * ST)              // 4608 floats
#define ATTN_SMEM ((QW + 4 * TB) * 4)    // 110592 bytes: Qs + 2xK + 2xV

__device__ __forceinline__ void stQK(float* buf, int r, int q4, float4 v) {
    int base = r * ST + q4;
    buf[base]      = v.x;
    buf[base + 18] = v.y;
    buf[base + 36] = v.z;
    buf[base + 54] = v.w;
}

__device__ __forceinline__ void stV(float* buf, int r, int q4, float4 v) {
    int r8  = r & 7;
    int kap = (r & ~7) | (r8 >> 1) | ((r8 & 1) << 2);
    int x   = kap & 3;
    float vv[4] = {v.x, v.y, v.z, v.w};
#pragma unroll
    for (int w = 0; w < 4; w++) {
        int c = 4 * q4 + w;
        int p = ((c & 7) << 3) | (c >> 3);
        int word = (((p >> 2) ^ x) << 2) | (p & 3);
        buf[kap * ST + word] = vv[w];
    }
}

__global__ void __launch_bounds__(256, 2)
attn_kernel(const float* __restrict__ mask, float* __restrict__ out)
{
    extern __shared__ float sm[];
    float* Qs = sm;                // [128][ST] mod4-major

    const int head = blockIdx.x;
    const int q0   = blockIdx.y * QTILE;
    const int b    = blockIdx.z;
    const int tid  = threadIdx.x;
    const int warp = tid >> 5, lane = tid & 31;
    const int g = lane >> 2, t = lane & 3;
    const int wq = warp * 16;

    // ---- prologue: Q tile (scaled by 1/8, tf32) + tile 0 of K/V ----
#pragma unroll
    for (int i = 0; i < 8; i++) {
        int linear = i * 256 + tid;
        int r = linear >> 4, q4 = linear & 15;
        float4 v = *(const float4*)(g_Qp + ((size_t)(b * SEQ) + q0 + r) * DMODEL + head * HDIM + 4 * q4);
        v.x *= 0.125f; v.y *= 0.125f; v.z *= 0.125f; v.w *= 0.125f;
        stQK(Qs, r, q4, to_tf32_4(v));
    }
#pragma unroll
    for (int i = 0; i < 4; i++) {
        int linear = i * 256 + tid;
        int r = linear >> 4, q4 = linear & 15;
        size_t goff = ((size_t)(b * SEQ) + r) * DMODEL + head * HDIM + 4 * q4;
        stQK(sm + QW, r, q4, to_tf32_4(*(const float4*)(g_Kp + goff)));
        stV(sm + QW + 2 * TB, r, q4, to_tf32_4(*(const float4*)(g_Vp + goff)));
    }

    float o[8][4];
#pragma unroll
    for (int j = 0; j < 8; j++)
#pragma unroll
        for (int c = 0; c < 4; c++) o[j][c] = 0.f;

    float m0r = -1e30f, m1r = -1e30f;
    float l0r = 0.f,    l1r = 0.f;

    const int NT = SEQ / KTILE;   // 32
    for (int kt = 0; kt < NT; kt++) {
        __syncthreads();   // buffer (kt&1) filled; previous readers done
        const float* Ks = sm + QW + (kt & 1) * TB;
        const float* Vs = sm + QW + 2 * TB + (kt & 1) * TB;
        const int k0 = kt * KTILE;

        // ---- S = Q @ K^T ----
        float s[8][4];
#pragma unroll
        for (int j = 0; j < 8; j++)
#pragma unroll
            for (int c = 0; c < 4; c++) s[j][c] = 0.f;

#pragma unroll
        for (int kk = 0; kk < 8; kk++) {
            float2 A0 = *(const float2*)(Qs + (wq + g) * ST + 18 * t + 2 * kk);
            float2 A1 = *(const float2*)(Qs + (wq + g + 8) * ST + 18 * t + 2 * kk);
#pragma unroll
            for (int j = 0; j < 8; j++) {
                float2 B = *(const float2*)(Ks + (8 * j + g) * ST + 18 * t + 2 * kk);
                mma_tf32(s[j], A0.x, A1.x, A0.y, A1.y, B.x, B.y);
            }
        }

        // ---- prefetch next K/V tile into registers (latency hidden by softmax+PV) ----
        float4 kst[4], vst[4];
        if (kt + 1 < NT) {
#pragma unroll
            for (int i = 0; i < 4; i++) {
                int linear = i * 256 + tid;
                int r = linear >> 4, q4 = linear & 15;
                size_t goff = ((size_t)(b * SEQ) + k0 + KTILE + r) * DMODEL + head * HDIM + 4 * q4;
                kst[i] = *(const float4*)(g_Kp + goff);
                vst[i] = *(const float4*)(g_Vp + goff);
            }
        }

        // ---- mask + online softmax ----
        const float* mrow0 = mask + ((size_t)(b * SEQ) + q0 + wq + g) * SEQ + k0;
        const float* mrow1 = mrow0 + (size_t)8 * SEQ;
        float rmax0 = -1e30f, rmax1 = -1e30f;
#pragma unroll
        for (int j = 0; j < 8; j++) {
            float2 mk0 = *(const float2*)(mrow0 + 8 * j + 2 * t);
            float2 mk1 = *(const float2*)(mrow1 + 8 * j + 2 * t);
            s[j][0] += mk0.x; s[j][1] += mk0.y;
            s[j][2] += mk1.x; s[j][3] += mk1.y;
            rmax0 = fmaxf(rmax0, fmaxf(s[j][0], s[j][1]));
            rmax1 = fmaxf(rmax1, fmaxf(s[j][2], s[j][3]));
        }
        rmax0 = fmaxf(rmax0, __shfl_xor_sync(0xffffffffu, rmax0, 1));
        rmax0 = fmaxf(rmax0, __shfl_xor_sync(0xffffffffu, rmax0, 2));
        rmax1 = fmaxf(rmax1, __shfl_xor_sync(0xffffffffu, rmax1, 1));
        rmax1 = fmaxf(rmax1, __shfl_xor_sync(0xffffffffu, rmax1, 2));

        float nm0 = fmaxf(m0r, rmax0), nm1 = fmaxf(m1r, rmax1);
        float alpha0 = __expf(m0r - nm0), alpha1 = __expf(m1r - nm1);
        m0r = nm0; m1r = nm1;

        float sum0 = 0.f, sum1 = 0.f;
#pragma unroll
        for (int j = 0; j < 8; j++) {
            s[j][0] = __expf(s[j][0] - nm0);
            s[j][1] = __expf(s[j][1] - nm0);
            s[j][2] = __expf(s[j][2] - nm1);
            s[j][3] = __expf(s[j][3] - nm1);
            sum0 += s[j][0] + s[j][1];
            sum1 += s[j][2] + s[j][3];
        }
        sum0 += __shfl_xor_sync(0xffffffffu, sum0, 1);
        sum0 += __shfl_xor_sync(0xffffffffu, sum0, 2);
        sum1 += __shfl_xor_sync(0xffffffffu, sum1, 1);
        sum1 += __shfl_xor_sync(0xffffffffu, sum1, 2);
        l0r = l0r * alpha0 + sum0;
        l1r = l1r * alpha1 + sum1;

#pragma unroll
        for (int j = 0; j < 8; j++) {
            o[j][0] *= alpha0; o[j][1] *= alpha0;
            o[j][2] *= alpha1; o[j][3] *= alpha1;
        }

        // ---- O += P @ V : P stays in registers (C-frag == A-frag on permuted V) ----
        const float4* V4 = (const float4*)Vs;
#pragma unroll
        for (int kk = 0; kk < 8; kk++) {
            float a0 = to_tf32(s[kk][0]);   // (g,   kappa=t)
            float a1 = to_tf32(s[kk][2]);   // (g+8, kappa=t)
            float a2 = to_tf32(s[kk][1]);   // (g,   kappa=t+4)
            float a3 = to_tf32(s[kk][3]);   // (g+8, kappa=t+4)
            int row0 = 8 * kk + t;
            float4 b0lo = V4[row0 * 18 + ((2 * g) ^ t)];
            float4 b0hi = V4[row0 * 18 + ((2 * g + 1) ^ t)];
            float4 b1lo = V4[(row0 + 4) * 18 + ((2 * g) ^ t)];
            float4 b1hi = V4[(row0 + 4) * 18 + ((2 * g + 1) ^ t)];
            mma_tf32(o[0], a0, a1, a2, a3, b0lo.x, b1lo.x);
            mma_tf32(o[1], a0, a1, a2, a3, b0lo.y, b1lo.y);
            mma_tf32(o[2], a0, a1, a2, a3, b0lo.z, b1lo.z);
            mma_tf32(o[3], a0, a1, a2, a3, b0lo.w, b1lo.w);
            mma_tf32(o[4], a0, a1, a2, a3, b0hi.x, b1hi.x);
            mma_tf32(o[5], a0, a1, a2, a3, b0hi.y, b1hi.y);
            mma_tf32(o[6], a0, a1, a2, a3, b0hi.z, b1hi.z);
            mma_tf32(o[7], a0, a1, a2, a3, b0hi.w, b1hi.w);
        }

        // ---- store staged tile into the other buffer ----
        if (kt + 1 < NT) {
            float* Kn = sm + QW + ((kt + 1) & 1) * TB;
            float* Vn = sm + QW + 2 * TB + ((kt + 1) & 1) * TB;
#pragma unroll
            for (int i = 0; i < 4; i++) {
                int linear = i * 256 + tid;
                int r = linear >> 4, q4 = linear & 15;
                stQK(Kn, r, q4, to_tf32_4(kst[i]));
                stV(Vn, r, q4, to_tf32_4(vst[i]));
            }
        }
    }

    // ---- epilogue ----
    float inv0 = 1.f / l0r, inv1 = 1.f / l1r;
#pragma unroll
    for (int j = 0; j < 8; j++) {
        int col = head * HDIM + j * 8 + 2 * t;
        size_t row0 = (size_t)(b * SEQ) + q0 + wq + g;
        float2 v0 = make_float2(o[j][0] * inv0, o[j][1] * inv0);
        float2 v1 = make_float2(o[j][2] * inv1, o[j][3] * inv1);
        *(float2*)(out + row0 * DMODEL + col)       = v0;
        *(float2*)(out + (row0 + 8) * DMODEL + col) = v1;
    }
}

// ================= launch =================
extern "C" void kernel_launch(void* const* d_in, const int* in_sizes, int n_in,
                              void* d_out, int out_size) {
    (void)in_sizes; (void)n_in; (void)out_size;
    const float* query = (const float*)d_in[0];
    const float* key   = (const float*)d_in[1];
    const float* value = (const float*)d_in[2];
    const float* mask  = (const float*)d_in[3];
    const float* Wq    = (const float*)d_in[4];
    const float* bq    = (const float*)d_in[5];
    const float* Wk    = (const float*)d_in[6];
    const float* bk    = (const float*)d_in[7];
    const float* Wv    = (const float*)d_in[8];
    const float* bv    = (const float*)d_in[9];
    float* out = (float*)d_out;

    cudaFuncSetAttribute(attn_kernel, cudaFuncAttributeMaxDynamicSharedMemorySize, ATTN_SMEM);

    dim3 pgrid(BATCH * SEQ / 128, DMODEL / 64, 3);   // (64, 12, 3)
    proj_kernel<<<pgrid, 256>>>(query, key, value, Wq, Wk, Wv, bq, bk, bv);

    dim3 agrid(NHEAD, SEQ / QTILE, BATCH);           // head fastest -> mask L2 reuse
    attn_kernel<<<agrid, 256, ATTN_SMEM>>>(mask, out);
}

// round 6
// speedup vs baseline: 1.4444x; 1.1916x over previous
#include <cuda_runtime.h>
#include <cstdint>

#define BATCH   4
#define NHEAD   12
#define HDIM    64
#define DMODEL  768
#define SEQ     2048

#define QTILE   128
#define KTILE   64
#define NQT     (SEQ / QTILE)     // 16
#define NKT     (SEQ / KTILE)     // 32

// tile layouts (floats)
#define QTW     (QTILE * 72)      // 9216  : word(r,c) = r*72 + 18*(c&3) + (c>>2)
#define KTW     (KTILE * 80)      // 5120  : word(r,c) = r*80 + 20*(c&3) + (c>>2)
#define VTW     (KTILE * 72)      // 4608  : kappa/sigma/xor permuted (see below)

// ---------------- static device scratch (pre-formatted, tf32-rounded) ----------------
__device__ float g_Qt[(size_t)BATCH * NHEAD * NQT * QTW];   // ~28 MB, Q pre-scaled by 0.125
__device__ float g_Kt[(size_t)BATCH * NHEAD * NKT * KTW];   // ~31 MB
__device__ float g_Vt[(size_t)BATCH * NHEAD * NKT * VTW];   // ~28 MB

// ---------------- helpers ----------------
__device__ __forceinline__ float to_tf32(float x) {
    unsigned u;
    asm("cvt.rna.tf32.f32 %0, %1;" : "=r"(u) : "f"(x));
    return __uint_as_float(u);
}
__device__ __forceinline__ float4 to_tf32_4(float4 v) {
    v.x = to_tf32(v.x); v.y = to_tf32(v.y);
    v.z = to_tf32(v.z); v.w = to_tf32(v.w);
    return v;
}

// D = A(16x8,row) * B(8x8,col) + C, tf32 in, f32 accum
// a0=(g,k=t) a1=(g+8,t) a2=(g,t+4) a3=(g+8,t+4); b0=(k=t,n=g) b1=(t+4,g)
__device__ __forceinline__ void mma_tf32(float c[4],
                                         float a0, float a1, float a2, float a3,
                                         float b0, float b1) {
    asm volatile(
        "mma.sync.aligned.m16n8k8.row.col.f32.tf32.tf32.f32 "
        "{%0,%1,%2,%3}, {%4,%5,%6,%7}, {%8,%9}, {%0,%1,%2,%3};\n"
        : "+f"(c[0]), "+f"(c[1]), "+f"(c[2]), "+f"(c[3])
        : "r"(__float_as_uint(a0)), "r"(__float_as_uint(a1)),
          "r"(__float_as_uint(a2)), "r"(__float_as_uint(a3)),
          "r"(__float_as_uint(b0)), "r"(__float_as_uint(b1)));
}

__device__ __forceinline__ unsigned smem_u32(const void* p) {
    unsigned a;
    asm("{ .reg .u64 t; cvta.to.shared.u64 t, %1; cvt.u32.u64 %0, t; }" : "=r"(a) : "l"(p));
    return a;
}
__device__ __forceinline__ void mbar_init(unsigned a, unsigned cnt) {
    asm volatile("mbarrier.init.shared.b64 [%0], %1;" :: "r"(a), "r"(cnt) : "memory");
}
__device__ __forceinline__ void mbar_expect(unsigned a, unsigned bytes) {
    asm volatile("mbarrier.arrive.expect_tx.shared.b64 _, [%0], %1;" :: "r"(a), "r"(bytes) : "memory");
}
__device__ __forceinline__ void bulk_g2s(unsigned dst, const float* src, unsigned bytes, unsigned mbar) {
    asm volatile(
        "cp.async.bulk.shared::cluster.global.mbarrier::complete_tx::bytes [%0], [%1], %2, [%3];"
        :: "r"(dst), "l"(__cvta_generic_to_global(src)), "r"(bytes), "r"(mbar) : "memory");
}
__device__ __forceinline__ void mbar_wait(unsigned a, unsigned parity) {
    asm volatile(
        "{\n\t.reg .pred P;\n\t"
        "WL%=:\n\t"
        "mbarrier.try_wait.parity.acquire.cta.shared::cta.b64 P, [%0], %1, 0x989680;\n\t"
        "@P bra WD%=;\n\t"
        "bra WL%=;\n\t"
        "WD%=:\n\t}"
        :: "r"(a), "r"(parity) : "memory");
}

// ================= projection GEMM (merged QKV, double-buffered, dynamic smem) =================
// smem (floats): Xs[2][128*36] at 0 and 4608; Ws[2][32*72] at 9216 and 11520. Total 13824 fl = 55296 B.
#define PJ_XS(s)  ((s) * 4608)
#define PJ_WS(s)  (9216 + (s) * 2304)
#define PROJ_SMEM (13824 * 4)

__global__ void __launch_bounds__(256, 2)
proj_kernel(const float* __restrict__ Xq, const float* __restrict__ Xk, const float* __restrict__ Xv,
            const float* __restrict__ Wqp, const float* __restrict__ Wkp, const float* __restrict__ Wvp,
            const float* __restrict__ bqp, const float* __restrict__ bkp, const float* __restrict__ bvp)
{
    extern __shared__ float psm[];

    const int sel = blockIdx.z;
    const float* X    = (sel == 0) ? Xq  : (sel == 1) ? Xk  : Xv;
    const float* W    = (sel == 0) ? Wqp : (sel == 1) ? Wkp : Wvp;
    const float* bias = (sel == 0) ? bqp : (sel == 1) ? bkp : bvp;

    const int tid  = threadIdx.x;
    const int warp = tid >> 5, lane = tid & 31;
    const int g = lane >> 2, t = lane & 3;
    const int m0 = blockIdx.x * 128;
    const int n0 = blockIdx.y * 64;
    const int head = blockIdx.y;
    const int wm = (warp & 3) * 32;
    const int wn = (warp >> 2) * 32;

    float4 xr[4], wr[2];
    // fill buffer 0
#pragma unroll
    for (int i = 0; i < 4; i++) {
        int lin = i * 256 + tid; int r = lin >> 3, c = (lin & 7) << 2;
        xr[i] = *(const float4*)(X + (size_t)(m0 + r) * DMODEL + c);
    }
#pragma unroll
    for (int i = 0; i < 2; i++) {
        int lin = i * 256 + tid; int r = lin >> 4, c = (lin & 15) << 2;
        wr[i] = *(const float4*)(W + (size_t)r * DMODEL + n0 + c);
    }
#pragma unroll
    for (int i = 0; i < 4; i++) {
        int lin = i * 256 + tid; int r = lin >> 3, c = (lin & 7) << 2;
        *(float4*)(psm + PJ_XS(0) + r * 36 + c) = to_tf32_4(xr[i]);
    }
#pragma unroll
    for (int i = 0; i < 2; i++) {
        int lin = i * 256 + tid; int r = lin >> 4, c = (lin & 15) << 2;
        *(float4*)(psm + PJ_WS(0) + r * 72 + c) = to_tf32_4(wr[i]);
    }
    __syncthreads();

    float acc[2][4][4];
#pragma unroll
    for (int mi = 0; mi < 2; mi++)
#pragma unroll
        for (int ni = 0; ni < 4; ni++)
#pragma unroll
            for (int c = 0; c < 4; c++) acc[mi][ni][c] = 0.f;

    const int NIT = DMODEL / 32;   // 24
    for (int it = 0; it < NIT; it++) {
        const int s = it & 1;
        const float* Xs = psm + PJ_XS(s);
        const float* Ws = psm + PJ_WS(s);
        if (it + 1 < NIT) {
            const int k0 = (it + 1) * 32;
#pragma unroll
            for (int i = 0; i < 4; i++) {
                int lin = i * 256 + tid; int r = lin >> 3, c = (lin & 7) << 2;
                xr[i] = *(const float4*)(X + (size_t)(m0 + r) * DMODEL + k0 + c);
            }
#pragma unroll
            for (int i = 0; i < 2; i++) {
                int lin = i * 256 + tid; int r = lin >> 4, c = (lin & 15) << 2;
                wr[i] = *(const float4*)(W + (size_t)(k0 + r) * DMODEL + n0 + c);
            }
        }

#pragma unroll
        for (int kk = 0; kk < 4; kk++) {
            int kb = kk * 8;
            float a[2][4];
#pragma unroll
            for (int mi = 0; mi < 2; mi++) {
                int rb = wm + mi * 16;
                a[mi][0] = Xs[(rb + g) * 36 + kb + t];
                a[mi][1] = Xs[(rb + g + 8) * 36 + kb + t];
                a[mi][2] = Xs[(rb + g) * 36 + kb + t + 4];
                a[mi][3] = Xs[(rb + g + 8) * 36 + kb + t + 4];
            }
#pragma unroll
            for (int ni = 0; ni < 4; ni++) {
                float b0 = Ws[(kb + t) * 72 + wn + ni * 8 + g];
                float b1 = Ws[(kb + t + 4) * 72 + wn + ni * 8 + g];
                mma_tf32(acc[0][ni], a[0][0], a[0][1], a[0][2], a[0][3], b0, b1);
                mma_tf32(acc[1][ni], a[1][0], a[1][1], a[1][2], a[1][3], b0, b1);
            }
        }

        if (it + 1 < NIT) {
            float* Xn = psm + PJ_XS(s ^ 1);
            float* Wn = psm + PJ_WS(s ^ 1);
#pragma unroll
            for (int i = 0; i < 4; i++) {
                int lin = i * 256 + tid; int r = lin >> 3, c = (lin & 7) << 2;
                *(float4*)(Xn + r * 36 + c) = to_tf32_4(xr[i]);
            }
#pragma unroll
            for (int i = 0; i < 2; i++) {
                int lin = i * 256 + tid; int r = lin >> 4, c = (lin & 15) << 2;
                *(float4*)(Wn + r * 72 + c) = to_tf32_4(wr[i]);
            }
        }
        __syncthreads();
    }

    // ---- epilogue: scatter into attention tile layouts, tf32-rounded ----
#pragma unroll
    for (int mi = 0; mi < 2; mi++) {
#pragma unroll
        for (int ni = 0; ni < 4; ni++) {
            int coll = wn + ni * 8 + 2 * t;      // 0..63 within head
            float b0v = bias[n0 + coll], b1v = bias[n0 + coll + 1];
            float vals[2][2] = {{acc[mi][ni][0] + b0v, acc[mi][ni][1] + b1v},
                                {acc[mi][ni][2] + b0v, acc[mi][ni][3] + b1v}};
#pragma unroll
            for (int rr = 0; rr < 2; rr++) {
                int row = m0 + wm + mi * 16 + g + rr * 8;
                int b = row >> 11, rm = row & 2047;
#pragma unroll
                for (int cc = 0; cc < 2; cc++) {
                    int c = coll + cc;
                    float v = vals[rr][cc];
                    if (sel == 0) {
                        int qt = rm >> 7, r = rm & 127;
                        size_t base = ((((size_t)b * NHEAD + head) * NQT) + qt) * QTW;
                        g_Qt[base + r * 72 + 18 * (c & 3) + (c >> 2)] = to_tf32(v * 0.125f);
                    } else if (sel == 1) {
                        int kt = rm >> 6, r = rm & 63;
                        size_t base = ((((size_t)b * NHEAD + head) * NKT) + kt) * KTW;
                        g_Kt[base + r * 80 + 20 * (c & 3) + (c >> 2)] = to_tf32(v);
                    } else {
                        int kt = rm >> 6, r = rm & 63;
                        int r8 = r & 7;
                        int kap = (r & ~7) | (r8 >> 1) | ((r8 & 1) << 2);
                        int p = ((c & 7) << 3) | (c >> 3);
                        int word = (((p >> 2) ^ (kap & 3)) << 2) | (p & 3);
                        size_t base = ((((size_t)b * NHEAD + head) * NKT) + kt) * VTW;
                        g_Vt[base + kap * 72 + word] = to_tf32(v);
                    }
                }
            }
        }
    }
}

// ================= flash attention (bulk-copy fed, double-buffered) =================
// smem (floats): Qs[0,9216) | K0[9216,14336) | K1[14336,19456) | V0[19456,24064) | V1[24064,28672)
#define SM_K0   9216
#define SM_V0   19456
#define ATTN_SMEM (28672 * 4)    // 114688 B -> 2 CTAs/SM

__global__ void __launch_bounds__(256, 2)
attn_kernel(const float* __restrict__ mask, float* __restrict__ out)
{
    extern __shared__ float sm[];
    __shared__ __align__(8) unsigned long long mbar[2];

    const int head = blockIdx.x;
    const int q0   = blockIdx.y * QTILE;
    const int b    = blockIdx.z;
    const int tid  = threadIdx.x;
    const int warp = tid >> 5, lane = tid & 31;
    const int g = lane >> 2, t = lane & 3;
    const int wq = warp * 16;

    const unsigned mb0 = smem_u32(&mbar[0]);
    const unsigned mb1 = smem_u32(&mbar[1]);
    const unsigned sQ  = smem_u32(sm);

    if (tid == 0) { mbar_init(mb0, 1); mbar_init(mb1, 1); }
    __syncthreads();

    const float* qsrc  = g_Qt + (((size_t)b * NHEAD + head) * NQT + blockIdx.y) * QTW;
    const float* kbase = g_Kt + (((size_t)b * NHEAD + head) * NKT) * KTW;
    const float* vbase = g_Vt + (((size_t)b * NHEAD + head) * NKT) * VTW;

    if (tid == 0) {
        mbar_expect(mb0, QTW * 4 + KTW * 4 + VTW * 4);
        bulk_g2s(sQ,              qsrc,  QTW * 4, mb0);
        bulk_g2s(sQ + SM_K0 * 4,  kbase, KTW * 4, mb0);
        bulk_g2s(sQ + SM_V0 * 4,  vbase, VTW * 4, mb0);
    }

    const float* Qs = sm;

    float o[8][4];
#pragma unroll
    for (int j = 0; j < 8; j++)
#pragma unroll
        for (int c = 0; c < 4; c++) o[j][c] = 0.f;

    float m0r = -1e30f, m1r = -1e30f;
    float l0r = 0.f,    l1r = 0.f;

    for (int kt = 0; kt < NKT; kt++) {
        const int s = kt & 1;

        // producer: fill the other stage for kt+1 (its readers finished at end of kt-1)
        if (tid == 0 && kt + 1 < NKT) {
            unsigned mbn = s ? mb0 : mb1;
            mbar_expect(mbn, KTW * 4 + VTW * 4);
            bulk_g2s(sQ + (SM_K0 + (s ^ 1) * KTW) * 4, kbase + (size_t)(kt + 1) * KTW, KTW * 4, mbn);
            bulk_g2s(sQ + (SM_V0 + (s ^ 1) * VTW) * 4, vbase + (size_t)(kt + 1) * VTW, VTW * 4, mbn);
        }

        mbar_wait(s ? mb1 : mb0, (kt >> 1) & 1);

        const float*  Ks = sm + SM_K0 + s * KTW;
        const float4* K4 = (const float4*)Ks;
        const float4* V4 = (const float4*)(sm + SM_V0 + s * VTW);
        const int k0 = kt * KTILE;

        // ---- S = Q @ K^T ----
        float sAcc[8][4];
#pragma unroll
        for (int j = 0; j < 8; j++)
#pragma unroll
            for (int c = 0; c < 4; c++) sAcc[j][c] = 0.f;

#pragma unroll
        for (int P = 0; P < 4; P++) {           // kk pair {2P, 2P+1}
            float2 Aa0 = *(const float2*)(Qs + (wq + g) * 72     + 18 * t + 4 * P);
            float2 Aa1 = *(const float2*)(Qs + (wq + g + 8) * 72 + 18 * t + 4 * P);
            float2 Ab0 = *(const float2*)(Qs + (wq + g) * 72     + 18 * t + 4 * P + 2);
            float2 Ab1 = *(const float2*)(Qs + (wq + g + 8) * 72 + 18 * t + 4 * P + 2);
#pragma unroll
            for (int j = 0; j < 8; j++) {
                float4 B = K4[(8 * j + g) * 20 + 5 * t + P];
                mma_tf32(sAcc[j], Aa0.x, Aa1.x, Aa0.y, Aa1.y, B.x, B.y);
                mma_tf32(sAcc[j], Ab0.x, Ab1.x, Ab0.y, Ab1.y, B.z, B.w);
            }
        }

        // ---- mask + online softmax ----
        const float* mrow0 = mask + ((size_t)(b * SEQ) + q0 + wq + g) * SEQ + k0;
        const float* mrow1 = mrow0 + (size_t)8 * SEQ;
        float rmax0 = -1e30f, rmax1 = -1e30f;
#pragma unroll
        for (int j = 0; j < 8; j++) {
            float2 mk0 = *(const float2*)(mrow0 + 8 * j + 2 * t);
            float2 mk1 = *(const float2*)(mrow1 + 8 * j + 2 * t);
            sAcc[j][0] += mk0.x; sAcc[j][1] += mk0.y;
            sAcc[j][2] += mk1.x; sAcc[j][3] += mk1.y;
            rmax0 = fmaxf(rmax0, fmaxf(sAcc[j][0], sAcc[j][1]));
            rmax1 = fmaxf(rmax1, fmaxf(sAcc[j][2], sAcc[j][3]));
        }
        rmax0 = fmaxf(rmax0, __shfl_xor_sync(0xffffffffu, rmax0, 1));
        rmax0 = fmaxf(rmax0, __shfl_xor_sync(0xffffffffu, rmax0, 2));
        rmax1 = fmaxf(rmax1, __shfl_xor_sync(0xffffffffu, rmax1, 1));
        rmax1 = fmaxf(rmax1, __shfl_xor_sync(0xffffffffu, rmax1, 2));

        float nm0 = fmaxf(m0r, rmax0), nm1 = fmaxf(m1r, rmax1);
        float alpha0 = __expf(m0r - nm0), alpha1 = __expf(m1r - nm1);
        m0r = nm0; m1r = nm1;

        float sum0 = 0.f, sum1 = 0.f;
#pragma unroll
        for (int j = 0; j < 8; j++) {
            sAcc[j][0] = __expf(sAcc[j][0] - nm0);
            sAcc[j][1] = __expf(sAcc[j][1] - nm0);
            sAcc[j][2] = __expf(sAcc[j][2] - nm1);
            sAcc[j][3] = __expf(sAcc[j][3] - nm1);
            sum0 += sAcc[j][0] + sAcc[j][1];
            sum1 += sAcc[j][2] + sAcc[j][3];
        }
        sum0 += __shfl_xor_sync(0xffffffffu, sum0, 1);
        sum0 += __shfl_xor_sync(0xffffffffu, sum0, 2);
        sum1 += __shfl_xor_sync(0xffffffffu, sum1, 1);
        sum1 += __shfl_xor_sync(0xffffffffu, sum1, 2);
        l0r = l0r * alpha0 + sum0;
        l1r = l1r * alpha1 + sum1;

#pragma unroll
        for (int j = 0; j < 8; j++) {
            o[j][0] *= alpha0; o[j][1] *= alpha0;
            o[j][2] *= alpha1; o[j][3] *= alpha1;
        }

        // ---- O += P @ V : P stays in registers (C-frag == A-frag on permuted V) ----
#pragma unroll
        for (int kk = 0; kk < 8; kk++) {
            float a0 = to_tf32(sAcc[kk][0]);   // (g,   kappa=t)
            float a1 = to_tf32(sAcc[kk][2]);   // (g+8, kappa=t)
            float a2 = to_tf32(sAcc[kk][1]);   // (g,   kappa=t+4)
            float a3 = to_tf32(sAcc[kk][3]);   // (g+8, kappa=t+4)
            int row0 = 8 * kk + t;
            float4 b0lo = V4[row0 * 18 + ((2 * g) ^ t)];
            float4 b0hi = V4[row0 * 18 + ((2 * g + 1) ^ t)];
            float4 b1lo = V4[(row0 + 4) * 18 + ((2 * g) ^ t)];
            float4 b1hi = V4[(row0 + 4) * 18 + ((2 * g + 1) ^ t)];
            mma_tf32(o[0], a0, a1, a2, a3, b0lo.x, b1lo.x);
            mma_tf32(o[1], a0, a1, a2, a3, b0lo.y, b1lo.y);
            mma_tf32(o[2], a0, a1, a2, a3, b0lo.z, b1lo.z);
            mma_tf32(o[3], a0, a1, a2, a3, b0lo.w, b1lo.w);
            mma_tf32(o[4], a0, a1, a2, a3, b0hi.x, b1hi.x);
            mma_tf32(o[5], a0, a1, a2, a3, b0hi.y, b1hi.y);
            mma_tf32(o[6], a0, a1, a2, a3, b0hi.z, b1hi.z);
            mma_tf32(o[7], a0, a1, a2, a3, b0hi.w, b1hi.w);
        }

        __syncthreads();   // all readers done with stage s before it is refilled at kt+2
    }

    // ---- epilogue ----
    float inv0 = 1.f / l0r, inv1 = 1.f / l1r;
#pragma unroll
    for (int j = 0; j < 8; j++) {
        int col = head * HDIM + j * 8 + 2 * t;
        size_t row0 = (size_t)(b * SEQ) + q0 + wq + g;
        float2 v0 = make_float2(o[j][0] * inv0, o[j][1] * inv0);
        float2 v1 = make_float2(o[j][2] * inv1, o[j][3] * inv1);
        *(float2*)(out + row0 * DMODEL + col)       = v0;
        *(float2*)(out + (row0 + 8) * DMODEL + col) = v1;
    }
}

// ================= launch =================
extern "C" void kernel_launch(void* const* d_in, const int* in_sizes, int n_in,
                              void* d_out, int out_size) {
    (void)in_sizes; (void)n_in; (void)out_size;
    const float* query = (const float*)d_in[0];
    const float* key   = (const float*)d_in[1];
    const float* value = (const float*)d_in[2];
    const float* mask  = (const float*)d_in[3];
    const float* Wq    = (const float*)d_in[4];
    const float* bq    = (const float*)d_in[5];
    const float* Wk    = (const float*)d_in[6];
    const float* bk    = (const float*)d_in[7];
    const float* Wv    = (const float*)d_in[8];
    const float* bv    = (const float*)d_in[9];
    float* out = (float*)d_out;

    cudaFuncSetAttribute(proj_kernel, cudaFuncAttributeMaxDynamicSharedMemorySize, PROJ_SMEM);
    cudaFuncSetAttribute(attn_kernel, cudaFuncAttributeMaxDynamicSharedMemorySize, ATTN_SMEM);

    dim3 pgrid(BATCH * SEQ / 128, NHEAD, 3);         // (64, 12, 3)
    proj_kernel<<<pgrid, 256, PROJ_SMEM>>>(query, key, value, Wq, Wk, Wv, bq, bk, bv);

    dim3 agrid(NHEAD, NQT, BATCH);                   // head fastest -> mask L2 reuse
    attn_kernel<<<agrid, 256, ATTN_SMEM>>>(mask, out);
}